// round 12
// baseline (speedup 1.0000x reference)
#include <cuda_runtime.h>
#include <cuda_fp16.h>
#include <cstdint>

#define N_USERS 50000
#define N_ITEMS 100000
#define N_NODES (N_USERS + N_ITEMS)
#define D 64
#define EPS 1e-6f
#define E_MAX 2400000
#define SCAN_BLOCK 1024
#define N_SCAN_BLOCKS ((N_NODES + SCAN_BLOCK - 1) / SCAN_BLOCK)   // 147

// ---------------------------------------------------------------------------
// Static scratch (allocation-free). Device symbols are ONLY referenced from
// device code. fp16-only embedding storage (R11 win): active set L2-resident,
// arithmetic fp32.
// ---------------------------------------------------------------------------
__device__ __half2 g_embh[4][N_NODES * D / 2];  // fp16 embeddings (layers 0..3)
__device__ int   g_cnt[N_NODES];               // per-row edge counts
__device__ int   g_row_ptr[N_NODES + 1];       // CSR row pointers
__device__ int   g_pos[E_MAX];                 // per-edge within-row rank (from hist)
__device__ int   g_csr_edge[E_MAX * 2];        // interleaved {col, val-bits} pairs
__device__ int   g_is64;                       // index dtype flag
__device__ int   g_done;                       // scan->scatter fence counter
// decoupled-lookback scan state (reset every launch by prep_init_kernel)
__device__ volatile int g_flag[N_SCAN_BLOCKS];
__device__ volatile int g_aggv[N_SCAN_BLOCKS];
__device__ volatile int g_incv[N_SCAN_BLOCKS];

// ---------------------------------------------------------------------------
// Prep + init fused: zero cnt/flags/done, detect index dtype, and write
// emb0 = fp16(concat(user_emb, item_emb)). Grid sized for the init work.
// ---------------------------------------------------------------------------
__global__ void prep_init_kernel(const float* __restrict__ user_emb,
                                 const float* __restrict__ item_emb,
                                 const void* rows, int n) {
    int i = blockIdx.x * blockDim.x + threadIdx.x;

    if (i < N_NODES) g_cnt[i] = 0;
    if (i < N_SCAN_BLOCKS) { g_flag[i] = 0; g_aggv[i] = 0; g_incv[i] = 0; }
    if (i == 0) g_done = 0;

    const int total4 = N_NODES * D / 4;
    if (i < total4) {
        const int usplit = N_USERS * D / 4;
        float4 v = (i < usplit) ? ((const float4*)user_emb)[i]
                                : ((const float4*)item_emb)[i - usplit];
        g_embh[0][i * 2]     = __floats2half2_rn(v.x, v.y);
        g_embh[0][i * 2 + 1] = __floats2half2_rn(v.z, v.w);
    }

    if (blockIdx.x == 0) {
        __shared__ int s_bad;
        if (threadIdx.x == 0) s_bad = 0;
        __syncthreads();
        int lim = (n < 64) ? n : 64;
        if ((int)threadIdx.x < lim) {
            long long v = ((const long long*)rows)[threadIdx.x];
            if (v < 0 || v >= (long long)N_NODES) atomicOr(&s_bad, 1);
        }
        __syncthreads();
        if (threadIdx.x == 0) g_is64 = s_bad ? 0 : 1;
    }
}

__device__ __forceinline__ int load_idx(const void* p, int e) {
    if (g_is64) return (int)((const long long*)p)[e];
    return ((const int*)p)[e];
}

// ---------------------------------------------------------------------------
// Histogram + rank stash (atomic return value = edge's within-row slot).
// ---------------------------------------------------------------------------
__global__ void hist_kernel(const void* __restrict__ rows, int n_edges) {
    int e = blockIdx.x * blockDim.x + threadIdx.x;
    if (e >= n_edges) return;
    int r = load_idx(rows, e);
    g_pos[e] = atomicAdd(&g_cnt[r], 1);
}

// ---------------------------------------------------------------------------
// Fused scan + scatter. Phase 1: decoupled-lookback exclusive scan of g_cnt
// -> g_row_ptr (warp-parallel lookback). Phase 2: after a grid-wide done-
// counter (147 resident blocks, deadlock-free), scatter edges into packed
// CSR slots atomic-free.
// ---------------------------------------------------------------------------
__global__ void scan_scatter_kernel(const void* __restrict__ rows,
                                    const void* __restrict__ cols,
                                    const float* __restrict__ vals,
                                    int n_edges) {
    __shared__ int sh[SCAN_BLOCK];
    __shared__ int s_exc;
    int b = blockIdx.x;
    int i = b * SCAN_BLOCK + threadIdx.x;
    int v = (i < N_NODES) ? g_cnt[i] : 0;
    sh[threadIdx.x] = v;
    __syncthreads();
    #pragma unroll
    for (int off = 1; off < SCAN_BLOCK; off <<= 1) {
        int t = (threadIdx.x >= off) ? sh[threadIdx.x - off] : 0;
        __syncthreads();
        sh[threadIdx.x] += t;
        __syncthreads();
    }
    int total = sh[SCAN_BLOCK - 1];

    if (threadIdx.x < 32) {                 // lookback warp
        int lane = threadIdx.x;
        if (b == 0) {
            if (lane == 0) {
                g_incv[0] = total;
                __threadfence();
                g_flag[0] = 2;
                s_exc = 0;
            }
        } else {
            if (lane == 0) {
                g_aggv[b] = total;
                __threadfence();
                g_flag[b] = 1;
            }
            int run = 0;
            int base = b;                    // window is [base-32, base)
            while (true) {
                int p = base - 32 + lane;
                int f, val;
                if (p >= 0) {
                    while ((f = g_flag[p]) == 0) { }
                    __threadfence();
                    val = (f == 2) ? g_incv[p] : g_aggv[p];
                } else {
                    f = 2; val = 0;
                }
                unsigned mask = __ballot_sync(0xFFFFFFFFu, f == 2);
                if (mask) {
                    int hi = 31 - __clz(mask);
                    int contrib = (lane >= hi) ? val : 0;
                    #pragma unroll
                    for (int o = 16; o; o >>= 1)
                        contrib += __shfl_xor_sync(0xFFFFFFFFu, contrib, o);
                    run += contrib;
                    break;
                } else {
                    int contrib = val;
                    #pragma unroll
                    for (int o = 16; o; o >>= 1)
                        contrib += __shfl_xor_sync(0xFFFFFFFFu, contrib, o);
                    run += contrib;
                    base -= 32;
                }
            }
            if (lane == 0) {
                g_incv[b] = run + total;
                __threadfence();
                g_flag[b] = 2;
                s_exc = run;
            }
        }
    }
    __syncthreads();

    if (i < N_NODES) {
        int inc = sh[threadIdx.x] + s_exc;
        g_row_ptr[i] = inc - v;              // exclusive
        if (i == N_NODES - 1) g_row_ptr[N_NODES] = inc;
    }
    __threadfence();                         // each writer publishes its row_ptr
    __syncthreads();

    // grid-wide fence: all row_ptr writes visible before any scatter
    if (threadIdx.x == 0) {
        atomicAdd(&g_done, 1);
        while (atomicAdd(&g_done, 0) < (int)gridDim.x) { }
    }
    __syncthreads();

    // Phase 2: scatter this block's edge slice (atomic-free, packed 8B store)
    int per = (n_edges + gridDim.x - 1) / gridDim.x;
    int s0 = b * per;
    int s1 = s0 + per; if (s1 > n_edges) s1 = n_edges;
    for (int e = s0 + threadIdx.x; e < s1; e += SCAN_BLOCK) {
        int r = load_idx(rows, e);
        int c = load_idx(cols, e);
        float vv = vals[e];
        int slot = __ldcg(&g_row_ptr[r]) + g_pos[e];   // L2-coherent read
        ((int2*)g_csr_edge)[slot] = make_int2(c, __float_as_int(vv));
    }
}

// ---------------------------------------------------------------------------
// Fused layer: per-node CSR gather-sum + growth gating. One warp per node;
// lane owns 2 dims. NEW: warp-cooperative edge prefetch — one coalesced
// LDG.64 loads 32 packed edges across lanes, __shfl broadcasts each edge
// (moves edge traffic off the LSU issue budget; gathers stay 2-in-flight).
// All arithmetic fp32; storage fp16.
// ---------------------------------------------------------------------------
__global__ void layer_kernel(int l) {
    int node = blockIdx.x * (blockDim.x >> 5) + (threadIdx.x >> 5);
    int lane = threadIdx.x & 31;
    if (node >= N_NODES) return;

    const __half2* baseh = g_embh[l];
    __half2*       outh  = g_embh[l + 1];

    int beg = __ldg(&g_row_ptr[node]);
    int end = __ldg(&g_row_ptr[node + 1]);
    int cnt = end - beg;

    float2 acc = make_float2(0.f, 0.f);

    for (int base = 0; base < cnt; base += 32) {
        int nrem = cnt - base; if (nrem > 32) nrem = 32;
        int2 ep = make_int2(0, 0);
        if (base + lane < cnt)
            ep = __ldg(&((const int2*)g_csr_edge)[beg + base + lane]);

        int j = 0;
        for (; j + 1 < nrem; j += 2) {
            int   c0 = __shfl_sync(0xFFFFFFFFu, ep.x, j);
            float v0 = __int_as_float(__shfl_sync(0xFFFFFFFFu, ep.y, j));
            int   c1 = __shfl_sync(0xFFFFFFFFu, ep.x, j + 1);
            float v1 = __int_as_float(__shfl_sync(0xFFFFFFFFu, ep.y, j + 1));
            float2 x0 = __half22float2(__ldg(&baseh[c0 * 32 + lane]));
            float2 x1 = __half22float2(__ldg(&baseh[c1 * 32 + lane]));
            acc.x += v0 * x0.x + v1 * x1.x;
            acc.y += v0 * x0.y + v1 * x1.y;
        }
        if (j < nrem) {
            int   c = __shfl_sync(0xFFFFFFFFu, ep.x, j);
            float v = __int_as_float(__shfl_sync(0xFFFFFFFFu, ep.y, j));
            float2 x = __half22float2(__ldg(&baseh[c * 32 + lane]));
            acc.x += v * x.x;
            acc.y += v * x.y;
        }
    }

    float2 o = __half22float2(baseh[node * 32 + lane]);

    float dx = o.x - acc.x + EPS;
    float dy = o.y - acc.y + EPS;
    float s = dx * dx + dy * dy;
    #pragma unroll
    for (int off = 16; off; off >>= 1)
        s += __shfl_xor_sync(0xFFFFFFFFu, s, off);

    float osn   = sqrtf(s);
    float dnew  = log1pf(osn);
    float inv   = 1.0f / (1.0f + dnew);
    float w_old = inv;
    float w_new = dnew * inv;

    float rx = w_old * o.x + w_new * acc.x;
    float ry = w_old * o.y + w_new * acc.y;
    outh[node * 32 + lane] = __floats2half2_rn(rx, ry);
}

// ---------------------------------------------------------------------------
// Gather: out row = fp32 mean over the 4 fp16 layer embeddings.
// ---------------------------------------------------------------------------
__global__ void gather_kernel(const void* __restrict__ user_id,
                              const void* __restrict__ item_id,
                              float* __restrict__ out,
                              int n_ids) {
    int i = blockIdx.x * (blockDim.x >> 5) + (threadIdx.x >> 5);
    int lane = threadIdx.x & 31;
    if (i >= 2 * n_ids) return;

    int node;
    if (i < n_ids) node = load_idx(user_id, i);
    else           node = N_USERS + load_idx(item_id, i - n_ids);

    int off = node * 32 + lane;
    float2 a0 = __half22float2(g_embh[0][off]);
    float2 a1 = __half22float2(g_embh[1][off]);
    float2 a2 = __half22float2(g_embh[2][off]);
    float2 a3 = __half22float2(g_embh[3][off]);
    float2 r;
    r.x = (a0.x + a1.x + a2.x + a3.x) * 0.25f;
    r.y = (a0.y + a1.y + a2.y + a3.y) * 0.25f;
    ((float2*)(out + (long long)i * D))[lane] = r;
}

// ---------------------------------------------------------------------------
// kernel_launch — stream order puts layer_kernel(0) at position 3 (the slot
// ncu profiles), so next round finally yields layer metrics.
// ---------------------------------------------------------------------------
extern "C" void kernel_launch(void* const* d_in, const int* in_sizes, int n_in,
                              void* d_out, int out_size) {
    const float* user_emb = (const float*)d_in[0];
    const float* item_emb = (const float*)d_in[1];
    const float* adj_vals = (const float*)d_in[2];
    const void*  adj_rows = d_in[3];
    const void*  adj_cols = d_in[4];
    const void*  user_id  = d_in[5];
    const void*  item_id  = d_in[6];
    float* out = (float*)d_out;

    int n_edges = in_sizes[3];
    if (n_edges > E_MAX) n_edges = E_MAX;
    int n_ids = in_sizes[5];

    // 0: prep + init (zero cnt/flags/done + dtype detect + emb0 fp16)
    {
        int total4 = N_NODES * D / 4;
        prep_init_kernel<<<(total4 + 255) / 256, 256>>>(user_emb, item_emb,
                                                        adj_rows, n_edges);
    }
    // 1: histogram + per-edge rank stash
    hist_kernel<<<(n_edges + 255) / 256, 256>>>(adj_rows, n_edges);
    // 2: fused scan + scatter
    scan_scatter_kernel<<<N_SCAN_BLOCKS, SCAN_BLOCK>>>(adj_rows, adj_cols,
                                                       adj_vals, n_edges);
    // 3-5: fused layers (warp per node, 8 nodes per 256-thread block)
    int layer_blocks = (N_NODES + 7) / 8;
    layer_kernel<<<layer_blocks, 256>>>(0);
    layer_kernel<<<layer_blocks, 256>>>(1);
    layer_kernel<<<layer_blocks, 256>>>(2);
    // 6: final gather + mean
    int gather_rows = 2 * n_ids;
    gather_kernel<<<(gather_rows + 7) / 8, 256>>>(user_id, item_id, out, n_ids);
}

// round 13
// speedup vs baseline: 1.0991x; 1.0991x over previous
#include <cuda_runtime.h>
#include <cuda_fp16.h>
#include <cstdint>

#define N_USERS 50000
#define N_ITEMS 100000
#define N_NODES (N_USERS + N_ITEMS)
#define D 64
#define EPS 1e-6f
#define E_MAX 2400000
#define SCAN_BLOCK 1024
#define N_SCAN_BLOCKS ((N_NODES + SCAN_BLOCK - 1) / SCAN_BLOCK)   // 147

// ---------------------------------------------------------------------------
// Static scratch (allocation-free). Device symbols are ONLY referenced from
// device code. fp16-only embedding storage (R11 win); arithmetic fp32.
// ---------------------------------------------------------------------------
__device__ __half2 g_embh[4][N_NODES * D / 2];  // fp16 embeddings (layers 0..3)
__device__ int   g_cnt[N_NODES];               // per-row edge counts
__device__ int   g_row_ptr[N_NODES + 1];       // CSR row pointers
__device__ int   g_pos[E_MAX];                 // per-edge within-row rank (from hist)
__device__ int   g_csr_edge[E_MAX * 2];        // interleaved {col, val-bits} pairs
__device__ int   g_is64;                       // index dtype flag
__device__ int   g_done;                       // scan->scatter fence counter
// decoupled-lookback scan state (reset every launch by prep_init_kernel)
__device__ volatile int g_flag[N_SCAN_BLOCKS];
__device__ volatile int g_aggv[N_SCAN_BLOCKS];
__device__ volatile int g_incv[N_SCAN_BLOCKS];

// ---------------------------------------------------------------------------
// Prep + init fused (R12 win): zero cnt/flags/done, detect index dtype, and
// write emb0 = fp16(concat(user_emb, item_emb)).
// ---------------------------------------------------------------------------
__global__ void prep_init_kernel(const float* __restrict__ user_emb,
                                 const float* __restrict__ item_emb,
                                 const void* rows, int n) {
    int i = blockIdx.x * blockDim.x + threadIdx.x;

    if (i < N_NODES) g_cnt[i] = 0;
    if (i < N_SCAN_BLOCKS) { g_flag[i] = 0; g_aggv[i] = 0; g_incv[i] = 0; }
    if (i == 0) g_done = 0;

    const int total4 = N_NODES * D / 4;
    if (i < total4) {
        const int usplit = N_USERS * D / 4;
        float4 v = (i < usplit) ? ((const float4*)user_emb)[i]
                                : ((const float4*)item_emb)[i - usplit];
        g_embh[0][i * 2]     = __floats2half2_rn(v.x, v.y);
        g_embh[0][i * 2 + 1] = __floats2half2_rn(v.z, v.w);
    }

    if (blockIdx.x == 0) {
        __shared__ int s_bad;
        if (threadIdx.x == 0) s_bad = 0;
        __syncthreads();
        int lim = (n < 64) ? n : 64;
        if ((int)threadIdx.x < lim) {
            long long v = ((const long long*)rows)[threadIdx.x];
            if (v < 0 || v >= (long long)N_NODES) atomicOr(&s_bad, 1);
        }
        __syncthreads();
        if (threadIdx.x == 0) g_is64 = s_bad ? 0 : 1;
    }
}

__device__ __forceinline__ int load_idx(const void* p, int e) {
    if (g_is64) return (int)((const long long*)p)[e];
    return ((const int*)p)[e];
}

// ---------------------------------------------------------------------------
// Histogram + rank stash (atomic return value = edge's within-row slot).
// ---------------------------------------------------------------------------
__global__ void hist_kernel(const void* __restrict__ rows, int n_edges) {
    int e = blockIdx.x * blockDim.x + threadIdx.x;
    if (e >= n_edges) return;
    int r = load_idx(rows, e);
    g_pos[e] = atomicAdd(&g_cnt[r], 1);
}

// ---------------------------------------------------------------------------
// Fused scan + scatter (R12 win). Phase 1: decoupled-lookback exclusive scan
// of g_cnt -> g_row_ptr. Phase 2: after grid-wide done-counter (147 resident
// blocks), scatter edges into packed CSR slots atomic-free.
// ---------------------------------------------------------------------------
__global__ void scan_scatter_kernel(const void* __restrict__ rows,
                                    const void* __restrict__ cols,
                                    const float* __restrict__ vals,
                                    int n_edges) {
    __shared__ int sh[SCAN_BLOCK];
    __shared__ int s_exc;
    int b = blockIdx.x;
    int i = b * SCAN_BLOCK + threadIdx.x;
    int v = (i < N_NODES) ? g_cnt[i] : 0;
    sh[threadIdx.x] = v;
    __syncthreads();
    #pragma unroll
    for (int off = 1; off < SCAN_BLOCK; off <<= 1) {
        int t = (threadIdx.x >= off) ? sh[threadIdx.x - off] : 0;
        __syncthreads();
        sh[threadIdx.x] += t;
        __syncthreads();
    }
    int total = sh[SCAN_BLOCK - 1];

    if (threadIdx.x < 32) {                 // lookback warp
        int lane = threadIdx.x;
        if (b == 0) {
            if (lane == 0) {
                g_incv[0] = total;
                __threadfence();
                g_flag[0] = 2;
                s_exc = 0;
            }
        } else {
            if (lane == 0) {
                g_aggv[b] = total;
                __threadfence();
                g_flag[b] = 1;
            }
            int run = 0;
            int base = b;                    // window is [base-32, base)
            while (true) {
                int p = base - 32 + lane;
                int f, val;
                if (p >= 0) {
                    while ((f = g_flag[p]) == 0) { }
                    __threadfence();
                    val = (f == 2) ? g_incv[p] : g_aggv[p];
                } else {
                    f = 2; val = 0;
                }
                unsigned mask = __ballot_sync(0xFFFFFFFFu, f == 2);
                if (mask) {
                    int hi = 31 - __clz(mask);
                    int contrib = (lane >= hi) ? val : 0;
                    #pragma unroll
                    for (int o = 16; o; o >>= 1)
                        contrib += __shfl_xor_sync(0xFFFFFFFFu, contrib, o);
                    run += contrib;
                    break;
                } else {
                    int contrib = val;
                    #pragma unroll
                    for (int o = 16; o; o >>= 1)
                        contrib += __shfl_xor_sync(0xFFFFFFFFu, contrib, o);
                    run += contrib;
                    base -= 32;
                }
            }
            if (lane == 0) {
                g_incv[b] = run + total;
                __threadfence();
                g_flag[b] = 2;
                s_exc = run;
            }
        }
    }
    __syncthreads();

    if (i < N_NODES) {
        int inc = sh[threadIdx.x] + s_exc;
        g_row_ptr[i] = inc - v;              // exclusive
        if (i == N_NODES - 1) g_row_ptr[N_NODES] = inc;
    }
    __threadfence();
    __syncthreads();

    // grid-wide fence: all row_ptr writes visible before any scatter
    if (threadIdx.x == 0) {
        atomicAdd(&g_done, 1);
        while (atomicAdd(&g_done, 0) < (int)gridDim.x) { }
    }
    __syncthreads();

    // Phase 2: scatter this block's edge slice (atomic-free, packed 8B store)
    int per = (n_edges + gridDim.x - 1) / gridDim.x;
    int s0 = b * per;
    int s1 = s0 + per; if (s1 > n_edges) s1 = n_edges;
    for (int e = s0 + threadIdx.x; e < s1; e += SCAN_BLOCK) {
        int r = load_idx(rows, e);
        int c = load_idx(cols, e);
        float vv = vals[e];
        int slot = __ldcg(&g_row_ptr[r]) + g_pos[e];
        ((int2*)g_csr_edge)[slot] = make_int2(c, __float_as_int(vv));
    }
}

// ---------------------------------------------------------------------------
// Fused layer — EXACT R11 form (measured ~52us/layer; R12's shfl-broadcast
// variant was issue-bound at 73.7us). One warp per node; lane owns 2 dims;
// 2-way unroll; scalar broadcast __ldg edge loads; fp32 math, fp16 storage.
// ---------------------------------------------------------------------------
__global__ void layer_kernel(int l) {
    int node = blockIdx.x * (blockDim.x >> 5) + (threadIdx.x >> 5);
    int lane = threadIdx.x & 31;
    if (node >= N_NODES) return;

    const __half2* baseh = g_embh[l];
    __half2*       outh  = g_embh[l + 1];

    int beg = __ldg(&g_row_ptr[node]);
    int end = __ldg(&g_row_ptr[node + 1]);

    float2 acc = make_float2(0.f, 0.f);

    int i = beg;
    for (; i + 1 < end; i += 2) {
        int   c0 = __ldg(&g_csr_edge[2 * i]);
        float v0 = __int_as_float(__ldg(&g_csr_edge[2 * i + 1]));
        int   c1 = __ldg(&g_csr_edge[2 * i + 2]);
        float v1 = __int_as_float(__ldg(&g_csr_edge[2 * i + 3]));
        float2 x0 = __half22float2(__ldg(&baseh[c0 * 32 + lane]));
        float2 x1 = __half22float2(__ldg(&baseh[c1 * 32 + lane]));
        acc.x += v0 * x0.x + v1 * x1.x;
        acc.y += v0 * x0.y + v1 * x1.y;
    }
    if (i < end) {
        int   c = __ldg(&g_csr_edge[2 * i]);
        float v = __int_as_float(__ldg(&g_csr_edge[2 * i + 1]));
        float2 x = __half22float2(__ldg(&baseh[c * 32 + lane]));
        acc.x += v * x.x;
        acc.y += v * x.y;
    }

    float2 o = __half22float2(baseh[node * 32 + lane]);

    float dx = o.x - acc.x + EPS;
    float dy = o.y - acc.y + EPS;
    float s = dx * dx + dy * dy;
    #pragma unroll
    for (int off = 16; off; off >>= 1)
        s += __shfl_xor_sync(0xFFFFFFFFu, s, off);

    float osn   = sqrtf(s);
    float dnew  = log1pf(osn);
    float inv   = 1.0f / (1.0f + dnew);
    float w_old = inv;
    float w_new = dnew * inv;

    float rx = w_old * o.x + w_new * acc.x;
    float ry = w_old * o.y + w_new * acc.y;
    outh[node * 32 + lane] = __floats2half2_rn(rx, ry);
}

// ---------------------------------------------------------------------------
// Gather: out row = fp32 mean over the 4 fp16 layer embeddings.
// ---------------------------------------------------------------------------
__global__ void gather_kernel(const void* __restrict__ user_id,
                              const void* __restrict__ item_id,
                              float* __restrict__ out,
                              int n_ids) {
    int i = blockIdx.x * (blockDim.x >> 5) + (threadIdx.x >> 5);
    int lane = threadIdx.x & 31;
    if (i >= 2 * n_ids) return;

    int node;
    if (i < n_ids) node = load_idx(user_id, i);
    else           node = N_USERS + load_idx(item_id, i - n_ids);

    int off = node * 32 + lane;
    float2 a0 = __half22float2(g_embh[0][off]);
    float2 a1 = __half22float2(g_embh[1][off]);
    float2 a2 = __half22float2(g_embh[2][off]);
    float2 a3 = __half22float2(g_embh[3][off]);
    float2 r;
    r.x = (a0.x + a1.x + a2.x + a3.x) * 0.25f;
    r.y = (a0.y + a1.y + a2.y + a3.y) * 0.25f;
    ((float2*)(out + (long long)i * D))[lane] = r;
}

// ---------------------------------------------------------------------------
// kernel_launch — layer_kernel(0) stays at stream position 3 (profiled slot).
// ---------------------------------------------------------------------------
extern "C" void kernel_launch(void* const* d_in, const int* in_sizes, int n_in,
                              void* d_out, int out_size) {
    const float* user_emb = (const float*)d_in[0];
    const float* item_emb = (const float*)d_in[1];
    const float* adj_vals = (const float*)d_in[2];
    const void*  adj_rows = d_in[3];
    const void*  adj_cols = d_in[4];
    const void*  user_id  = d_in[5];
    const void*  item_id  = d_in[6];
    float* out = (float*)d_out;

    int n_edges = in_sizes[3];
    if (n_edges > E_MAX) n_edges = E_MAX;
    int n_ids = in_sizes[5];

    // 0: prep + init (zero cnt/flags/done + dtype detect + emb0 fp16)
    {
        int total4 = N_NODES * D / 4;
        prep_init_kernel<<<(total4 + 255) / 256, 256>>>(user_emb, item_emb,
                                                        adj_rows, n_edges);
    }
    // 1: histogram + per-edge rank stash
    hist_kernel<<<(n_edges + 255) / 256, 256>>>(adj_rows, n_edges);
    // 2: fused scan + scatter
    scan_scatter_kernel<<<N_SCAN_BLOCKS, SCAN_BLOCK>>>(adj_rows, adj_cols,
                                                       adj_vals, n_edges);
    // 3-5: fused layers (warp per node, 8 nodes per 256-thread block)
    int layer_blocks = (N_NODES + 7) / 8;
    layer_kernel<<<layer_blocks, 256>>>(0);
    layer_kernel<<<layer_blocks, 256>>>(1);
    layer_kernel<<<layer_blocks, 256>>>(2);
    // 6: final gather + mean
    int gather_rows = 2 * n_ids;
    gather_kernel<<<(gather_rows + 7) / 8, 256>>>(user_id, item_id, out, n_ids);
}

// round 14
// speedup vs baseline: 1.4268x; 1.2981x over previous
#include <cuda_runtime.h>
#include <cuda_fp16.h>
#include <cstdint>

#define N_USERS 50000
#define N_ITEMS 100000
#define N_NODES (N_USERS + N_ITEMS)
#define D 64
#define EPS 1e-6f
#define E_MAX 2400000
#define SCAN_BLOCK 1024
#define N_SCAN_BLOCKS ((N_NODES + SCAN_BLOCK - 1) / SCAN_BLOCK)   // 147

// ---------------------------------------------------------------------------
// Static scratch (allocation-free). Device symbols are ONLY referenced from
// device code. fp16-only embedding storage (R11 win); arithmetic fp32.
// ---------------------------------------------------------------------------
__device__ __half2 g_embh[4][N_NODES * D / 2];  // fp16 embeddings (layers 0..3)
__device__ int   g_cnt[N_NODES];               // per-row edge counts
__device__ int   g_row_ptr[N_NODES + 1];       // CSR row pointers
__device__ int   g_pos[E_MAX];                 // per-edge within-row rank (from hist)
__device__ int   g_csr_edge[E_MAX * 2];        // interleaved {col, val-bits} pairs
__device__ int   g_is64;                       // index dtype flag
__device__ int   g_done;                       // scan->scatter fence counter
// decoupled-lookback scan state (reset every launch by prep_init_kernel)
__device__ volatile int g_flag[N_SCAN_BLOCKS];
__device__ volatile int g_aggv[N_SCAN_BLOCKS];
__device__ volatile int g_incv[N_SCAN_BLOCKS];

// ---------------------------------------------------------------------------
// Prep + init fused (R12 win): zero cnt/flags/done, detect index dtype, and
// write emb0 = fp16(concat(user_emb, item_emb)).
// ---------------------------------------------------------------------------
__global__ void prep_init_kernel(const float* __restrict__ user_emb,
                                 const float* __restrict__ item_emb,
                                 const void* rows, int n) {
    int i = blockIdx.x * blockDim.x + threadIdx.x;

    if (i < N_NODES) g_cnt[i] = 0;
    if (i < N_SCAN_BLOCKS) { g_flag[i] = 0; g_aggv[i] = 0; g_incv[i] = 0; }
    if (i == 0) g_done = 0;

    const int total4 = N_NODES * D / 4;
    if (i < total4) {
        const int usplit = N_USERS * D / 4;
        float4 v = (i < usplit) ? ((const float4*)user_emb)[i]
                                : ((const float4*)item_emb)[i - usplit];
        g_embh[0][i * 2]     = __floats2half2_rn(v.x, v.y);
        g_embh[0][i * 2 + 1] = __floats2half2_rn(v.z, v.w);
    }

    if (blockIdx.x == 0) {
        __shared__ int s_bad;
        if (threadIdx.x == 0) s_bad = 0;
        __syncthreads();
        int lim = (n < 64) ? n : 64;
        if ((int)threadIdx.x < lim) {
            long long v = ((const long long*)rows)[threadIdx.x];
            if (v < 0 || v >= (long long)N_NODES) atomicOr(&s_bad, 1);
        }
        __syncthreads();
        if (threadIdx.x == 0) g_is64 = s_bad ? 0 : 1;
    }
}

__device__ __forceinline__ int load_idx(const void* p, int e) {
    if (g_is64) return (int)((const long long*)p)[e];
    return ((const int*)p)[e];
}

// ---------------------------------------------------------------------------
// Histogram + rank stash (atomic return value = edge's within-row slot).
// ---------------------------------------------------------------------------
__global__ void hist_kernel(const void* __restrict__ rows, int n_edges) {
    int e = blockIdx.x * blockDim.x + threadIdx.x;
    if (e >= n_edges) return;
    int r = load_idx(rows, e);
    g_pos[e] = atomicAdd(&g_cnt[r], 1);
}

// ---------------------------------------------------------------------------
// Fused scan + scatter (R12 win). Phase 1: decoupled-lookback exclusive scan
// of g_cnt -> g_row_ptr. Phase 2: after grid-wide done-counter (147 resident
// blocks), scatter edges into packed CSR slots atomic-free.
// ---------------------------------------------------------------------------
__global__ void scan_scatter_kernel(const void* __restrict__ rows,
                                    const void* __restrict__ cols,
                                    const float* __restrict__ vals,
                                    int n_edges) {
    __shared__ int sh[SCAN_BLOCK];
    __shared__ int s_exc;
    int b = blockIdx.x;
    int i = b * SCAN_BLOCK + threadIdx.x;
    int v = (i < N_NODES) ? g_cnt[i] : 0;
    sh[threadIdx.x] = v;
    __syncthreads();
    #pragma unroll
    for (int off = 1; off < SCAN_BLOCK; off <<= 1) {
        int t = (threadIdx.x >= off) ? sh[threadIdx.x - off] : 0;
        __syncthreads();
        sh[threadIdx.x] += t;
        __syncthreads();
    }
    int total = sh[SCAN_BLOCK - 1];

    if (threadIdx.x < 32) {                 // lookback warp
        int lane = threadIdx.x;
        if (b == 0) {
            if (lane == 0) {
                g_incv[0] = total;
                __threadfence();
                g_flag[0] = 2;
                s_exc = 0;
            }
        } else {
            if (lane == 0) {
                g_aggv[b] = total;
                __threadfence();
                g_flag[b] = 1;
            }
            int run = 0;
            int base = b;                    // window is [base-32, base)
            while (true) {
                int p = base - 32 + lane;
                int f, val;
                if (p >= 0) {
                    while ((f = g_flag[p]) == 0) { }
                    __threadfence();
                    val = (f == 2) ? g_incv[p] : g_aggv[p];
                } else {
                    f = 2; val = 0;
                }
                unsigned mask = __ballot_sync(0xFFFFFFFFu, f == 2);
                if (mask) {
                    int hi = 31 - __clz(mask);
                    int contrib = (lane >= hi) ? val : 0;
                    #pragma unroll
                    for (int o = 16; o; o >>= 1)
                        contrib += __shfl_xor_sync(0xFFFFFFFFu, contrib, o);
                    run += contrib;
                    break;
                } else {
                    int contrib = val;
                    #pragma unroll
                    for (int o = 16; o; o >>= 1)
                        contrib += __shfl_xor_sync(0xFFFFFFFFu, contrib, o);
                    run += contrib;
                    base -= 32;
                }
            }
            if (lane == 0) {
                g_incv[b] = run + total;
                __threadfence();
                g_flag[b] = 2;
                s_exc = run;
            }
        }
    }
    __syncthreads();

    if (i < N_NODES) {
        int inc = sh[threadIdx.x] + s_exc;
        g_row_ptr[i] = inc - v;              // exclusive
        if (i == N_NODES - 1) g_row_ptr[N_NODES] = inc;
    }
    __threadfence();
    __syncthreads();

    // grid-wide fence: all row_ptr writes visible before any scatter
    if (threadIdx.x == 0) {
        atomicAdd(&g_done, 1);
        while (atomicAdd(&g_done, 0) < (int)gridDim.x) { }
    }
    __syncthreads();

    // Phase 2: scatter this block's edge slice (atomic-free, packed 8B store)
    int per = (n_edges + gridDim.x - 1) / gridDim.x;
    int s0 = b * per;
    int s1 = s0 + per; if (s1 > n_edges) s1 = n_edges;
    for (int e = s0 + threadIdx.x; e < s1; e += SCAN_BLOCK) {
        int r = load_idx(rows, e);
        int c = load_idx(cols, e);
        float vv = vals[e];
        int slot = __ldcg(&g_row_ptr[r]) + g_pos[e];
        ((int2*)g_csr_edge)[slot] = make_int2(c, __float_as_int(vv));
    }
}

// ---------------------------------------------------------------------------
// Fused layer — 4 nodes/warp, 8 lanes/node, 8 dims/lane. One LDG.128 gathers
// four nodes' row slices per iteration; one 8-lane-uniform LDG.64 fetches
// each node's current edge. Math stays fp32; storage fp16. Cuts warp issue
// slots/edge ~10 -> ~7 (layer was measured issue-bound: 62.7% issue, 7.7% DRAM).
// ---------------------------------------------------------------------------
__global__ void layer_kernel(int l) {
    int warp = blockIdx.x * (blockDim.x >> 5) + (threadIdx.x >> 5);
    int lane = threadIdx.x & 31;
    int grp  = lane >> 3;          // node within warp (0..3)
    int sub  = lane & 7;           // 16B slice within 128B row
    int node = warp * 4 + grp;
    if (node >= N_NODES) return;   // whole warp exits together (N_NODES%4==0)

    const char* baseb = (const char*)g_embh[l];
    char*       outb  = (char*)g_embh[l + 1];
    int slice = sub * 16;

    int beg = __ldg(&g_row_ptr[node]);
    int end = __ldg(&g_row_ptr[node + 1]);

    float acc[8];
    #pragma unroll
    for (int k = 0; k < 8; k++) acc[k] = 0.f;

    for (int i = beg; i < end; i++) {
        int2 e = __ldg(&((const int2*)g_csr_edge)[i]);
        float v = __int_as_float(e.y);
        uint4 raw = __ldg((const uint4*)(baseb + (size_t)e.x * 128 + slice));
        float2 f0 = __half22float2(*(__half2*)&raw.x);
        float2 f1 = __half22float2(*(__half2*)&raw.y);
        float2 f2 = __half22float2(*(__half2*)&raw.z);
        float2 f3 = __half22float2(*(__half2*)&raw.w);
        acc[0] += v * f0.x;  acc[1] += v * f0.y;
        acc[2] += v * f1.x;  acc[3] += v * f1.y;
        acc[4] += v * f2.x;  acc[5] += v * f2.y;
        acc[6] += v * f3.x;  acc[7] += v * f3.y;
    }

    // self row slice
    uint4 so = __ldg((const uint4*)(baseb + (size_t)node * 128 + slice));
    float o[8];
    {
        float2 f0 = __half22float2(*(__half2*)&so.x);
        float2 f1 = __half22float2(*(__half2*)&so.y);
        float2 f2 = __half22float2(*(__half2*)&so.z);
        float2 f3 = __half22float2(*(__half2*)&so.w);
        o[0] = f0.x; o[1] = f0.y; o[2] = f1.x; o[3] = f1.y;
        o[4] = f2.x; o[5] = f2.y; o[6] = f3.x; o[7] = f3.y;
    }

    float s = 0.f;
    #pragma unroll
    for (int k = 0; k < 8; k++) {
        float d = o[k] - acc[k] + EPS;
        s += d * d;
    }
    __syncwarp();
    // reduce over the 8 lanes of this node (xor offsets stay in-group)
    s += __shfl_xor_sync(0xFFFFFFFFu, s, 1);
    s += __shfl_xor_sync(0xFFFFFFFFu, s, 2);
    s += __shfl_xor_sync(0xFFFFFFFFu, s, 4);

    float osn   = sqrtf(s);
    float dnew  = log1pf(osn);
    float inv   = 1.0f / (1.0f + dnew);
    float w_old = inv;
    float w_new = dnew * inv;

    uint4 outv;
    ((__half2*)&outv.x)[0] = __floats2half2_rn(w_old * o[0] + w_new * acc[0],
                                               w_old * o[1] + w_new * acc[1]);
    ((__half2*)&outv.y)[0] = __floats2half2_rn(w_old * o[2] + w_new * acc[2],
                                               w_old * o[3] + w_new * acc[3]);
    ((__half2*)&outv.z)[0] = __floats2half2_rn(w_old * o[4] + w_new * acc[4],
                                               w_old * o[5] + w_new * acc[5]);
    ((__half2*)&outv.w)[0] = __floats2half2_rn(w_old * o[6] + w_new * acc[6],
                                               w_old * o[7] + w_new * acc[7]);
    *(uint4*)(outb + (size_t)node * 128 + slice) = outv;
}

// ---------------------------------------------------------------------------
// Gather: out row = fp32 mean over the 4 fp16 layer embeddings.
// ---------------------------------------------------------------------------
__global__ void gather_kernel(const void* __restrict__ user_id,
                              const void* __restrict__ item_id,
                              float* __restrict__ out,
                              int n_ids) {
    int i = blockIdx.x * (blockDim.x >> 5) + (threadIdx.x >> 5);
    int lane = threadIdx.x & 31;
    if (i >= 2 * n_ids) return;

    int node;
    if (i < n_ids) node = load_idx(user_id, i);
    else           node = N_USERS + load_idx(item_id, i - n_ids);

    int off = node * 32 + lane;
    float2 a0 = __half22float2(g_embh[0][off]);
    float2 a1 = __half22float2(g_embh[1][off]);
    float2 a2 = __half22float2(g_embh[2][off]);
    float2 a3 = __half22float2(g_embh[3][off]);
    float2 r;
    r.x = (a0.x + a1.x + a2.x + a3.x) * 0.25f;
    r.y = (a0.y + a1.y + a2.y + a3.y) * 0.25f;
    ((float2*)(out + (long long)i * D))[lane] = r;
}

// ---------------------------------------------------------------------------
// kernel_launch — layer_kernel(0) stays at stream position 3 (profiled slot).
// ---------------------------------------------------------------------------
extern "C" void kernel_launch(void* const* d_in, const int* in_sizes, int n_in,
                              void* d_out, int out_size) {
    const float* user_emb = (const float*)d_in[0];
    const float* item_emb = (const float*)d_in[1];
    const float* adj_vals = (const float*)d_in[2];
    const void*  adj_rows = d_in[3];
    const void*  adj_cols = d_in[4];
    const void*  user_id  = d_in[5];
    const void*  item_id  = d_in[6];
    float* out = (float*)d_out;

    int n_edges = in_sizes[3];
    if (n_edges > E_MAX) n_edges = E_MAX;
    int n_ids = in_sizes[5];

    // 0: prep + init (zero cnt/flags/done + dtype detect + emb0 fp16)
    {
        int total4 = N_NODES * D / 4;
        prep_init_kernel<<<(total4 + 255) / 256, 256>>>(user_emb, item_emb,
                                                        adj_rows, n_edges);
    }
    // 1: histogram + per-edge rank stash
    hist_kernel<<<(n_edges + 255) / 256, 256>>>(adj_rows, n_edges);
    // 2: fused scan + scatter
    scan_scatter_kernel<<<N_SCAN_BLOCKS, SCAN_BLOCK>>>(adj_rows, adj_cols,
                                                       adj_vals, n_edges);
    // 3-5: fused layers (4 nodes per warp, 8 warps per block)
    {
        int warps = (N_NODES + 3) / 4;
        int layer_blocks = (warps + 7) / 8;
        layer_kernel<<<layer_blocks, 256>>>(0);
        layer_kernel<<<layer_blocks, 256>>>(1);
        layer_kernel<<<layer_blocks, 256>>>(2);
    }
    // 6: final gather + mean
    int gather_rows = 2 * n_ids;
    gather_kernel<<<(gather_rows + 7) / 8, 256>>>(user_id, item_id, out, n_ids);
}